// round 15
// baseline (speedup 1.0000x reference)
#include <cuda_runtime.h>
#include <cuda_bf16.h>
#include <cstdint>

#define BATCH  4096
#define HID    512
#define NATOMS 262144
#define KG     1024
#define NG     2048

// ---------------- device scratch (no allocations allowed) ----------------
__device__ __align__(128) float g_c[BATCH * HID];     // c state [m][j]
__device__ __align__(128) float g_z[BATCH * NG];      // z = q@U scratch [m][4H] natural
__device__ __align__(128) __nv_bfloat16 g_qhi[BATCH * KG];  // q_star hi split [m][k]
__device__ __align__(128) __nv_bfloat16 g_qlo[BATCH * KG];  // q_star lo split
__device__ __align__(128) __nv_bfloat16 g_Bhi[NG * KG];     // U^T hi split [n][k] (natural n)
__device__ __align__(128) __nv_bfloat16 g_Blo[NG * KG];
__device__ int g_segoff[BATCH + 1];

// ---------------- helpers ----------------
__device__ __forceinline__ uint32_t smem_u32(const void* p) {
    uint32_t a;
    asm("{ .reg .u64 t; cvta.to.shared.u64 t, %1; cvt.u32.u64 %0, t; }" : "=r"(a) : "l"(p));
    return a;
}
__device__ __forceinline__ void cp16(uint32_t dst, const void* src) {
    asm volatile("cp.async.cg.shared.global [%0], [%1], 16;" :: "r"(dst), "l"(src));
}
__device__ __forceinline__ void cp_commit() {
    asm volatile("cp.async.commit_group;" ::: "memory");
}
#define MMA16816(d, a, b) \
    asm volatile("mma.sync.aligned.m16n8k16.row.col.f32.bf16.bf16.f32 " \
        "{%0,%1,%2,%3}, {%4,%5,%6,%7}, {%8,%9}, {%0,%1,%2,%3};" \
        : "+f"((d)[0]), "+f"((d)[1]), "+f"((d)[2]), "+f"((d)[3]) \
        : "r"((a)[0]), "r"((a)[1]), "r"((a)[2]), "r"((a)[3]), \
          "r"((b)[0]), "r"((b)[1]))
#define LDSM4(r, a) \
    asm volatile("ldmatrix.sync.aligned.m8n8.x4.shared.b16 {%0,%1,%2,%3}, [%4];" \
        : "=r"((r)[0]), "=r"((r)[1]), "=r"((r)[2]), "=r"((r)[3]) : "r"(a))

// ---------------- init / offsets / prep ----------------
__global__ void k_init() {
    int i = blockIdx.x * blockDim.x + threadIdx.x;
    int n = blockDim.x * gridDim.x;
    __nv_bfloat16 z = __float2bfloat16(0.f);
    for (int t = i; t < BATCH * HID; t += n) {
        g_c[t] = 0.f;
        int m = t >> 9, j = t & 511;
        g_qhi[(size_t)m * KG + j] = z;   // h part; r part written by attention
        g_qlo[(size_t)m * KG + j] = z;
    }
}

// dtype-agnostic segment offsets (atom_split may be int32 or int64)
__global__ void k_off(const int* __restrict__ s32) {
    __shared__ int is64;
    if (threadIdx.x == 0)
        is64 = (s32[2 * (NATOMS / 4) + 1] == 0) ? 1 : 0;
    __syncthreads();
    int b = blockIdx.x * blockDim.x + threadIdx.x;
    if (b > BATCH) return;
    int lo = 0, hi = NATOMS;
    while (lo < hi) {
        int mid = (lo + hi) >> 1;
        int v = is64 ? s32[2 * mid] : s32[mid];
        if (v < b) lo = mid + 1; else hi = mid;
    }
    g_segoff[b] = lo;
}

// B prep: tiled transpose + split; coalesced reads AND (64B-segment) writes
__global__ __launch_bounds__(256) void k_prep(const float* __restrict__ U) {
    __shared__ float tile[32][33];
    int k0 = blockIdx.x * 32, n0 = blockIdx.y * 32;
    int tx = threadIdx.x & 31, ty = threadIdx.x >> 5;   // ty 0..7
    #pragma unroll
    for (int dy = 0; dy < 32; dy += 8)
        tile[ty + dy][tx] = U[(size_t)(k0 + ty + dy) * NG + n0 + tx];
    __syncthreads();
    #pragma unroll
    for (int dy = 0; dy < 32; dy += 8) {
        int n = n0 + ty + dy, k = k0 + tx;
        float v = tile[tx][ty + dy];
        __nv_bfloat16 hi = __float2bfloat16(v);
        g_Bhi[(size_t)n * KG + k] = hi;
        g_Blo[(size_t)n * KG + k] = __float2bfloat16(v - __bfloat162float(hi));
    }
}

// ---------------- fused attention (+LSTM prologue) ----------------
// mode: 0 = first iter (h = 0), 1 = mid (LSTM prologue, write q splits),
//       2 = final (LSTM prologue, write h half of out; r half of out from attention)
__global__ __launch_bounds__(128, 8) void k_attn(const float* __restrict__ X,
                                                 const float* __restrict__ bias,
                                                 float* __restrict__ out, int mode) {
    int b = blockIdx.x, t = threadIdx.x;
    int lane = t & 31, w = t >> 5;
    __shared__ float sm_h[512];

    // ---- LSTM prologue (math verbatim from verified k_lstm; CTA owns row b) ----
    if (mode != 0) {
        const float* zr = g_z + (size_t)b * NG;
        float* cr = g_c + (size_t)b * HID;
        #pragma unroll
        for (int u = 0; u < 4; u++) {
            int j = t + u * 128;
            float zi = zr[j]        + bias[j];
            float zf = zr[512 + j]  + bias[512 + j];
            float zo = zr[1024 + j] + bias[1024 + j];
            float zg = zr[1536 + j] + bias[1536 + j];
            float gi = 1.f / (1.f + expf(-zi));
            float gf = 1.f / (1.f + expf(-zf));
            float go = 1.f / (1.f + expf(-zo));
            float c  = gf * cr[j] + gi * tanhf(zg);
            cr[j] = c;
            float h = go * tanhf(c);
            sm_h[j] = h;
            if (mode == 2) {
                out[(size_t)b * 1024 + j] = h;
            } else {
                __nv_bfloat16 hi = __float2bfloat16(h);
                g_qhi[(size_t)b * KG + j] = hi;
                g_qlo[(size_t)b * KG + j] = __float2bfloat16(h - __bfloat162float(hi));
            }
        }
    } else {
        #pragma unroll
        for (int u = 0; u < 4; u++) sm_h[t + u * 128] = 0.f;
    }
    __syncthreads();

    int s = g_segoff[b], e = g_segoff[b + 1];
    float4 h4[4];
    #pragma unroll
    for (int q = 0; q < 4; q++)
        h4[q] = *(const float4*)&sm_h[q * 128 + lane * 4];

    float mval = -1e30f, den = 0.f;
    float4 r4[4];
    #pragma unroll
    for (int q = 0; q < 4; q++) { r4[q].x = 0.f; r4[q].y = 0.f; r4[q].z = 0.f; r4[q].w = 0.f; }

    for (int a = s + w; a < e; a += 4) {
        const float* xr = X + (size_t)a * HID;
        float4 x4[4];
        #pragma unroll
        for (int q = 0; q < 4; q++)
            x4[q] = *(const float4*)(xr + q * 128 + lane * 4);
        float p = 0.f;
        #pragma unroll
        for (int q = 0; q < 4; q++)
            p += x4[q].x * h4[q].x + x4[q].y * h4[q].y + x4[q].z * h4[q].z + x4[q].w * h4[q].w;
        #pragma unroll
        for (int o = 16; o; o >>= 1) p += __shfl_xor_sync(0xffffffffu, p, o);
        float mn = fmaxf(mval, p);
        float sc = expf(mval - mn);
        float pw = expf(p - mn);
        den = den * sc + pw;
        #pragma unroll
        for (int q = 0; q < 4; q++) {
            r4[q].x = r4[q].x * sc + pw * x4[q].x;
            r4[q].y = r4[q].y * sc + pw * x4[q].y;
            r4[q].z = r4[q].z * sc + pw * x4[q].z;
            r4[q].w = r4[q].w * sc + pw * x4[q].w;
        }
        mval = mn;
    }

    __shared__ float sm_m[4], sm_d[4];
    __shared__ float sm_r[4][512];
    if (lane == 0) { sm_m[w] = mval; sm_d[w] = den; }
    #pragma unroll
    for (int q = 0; q < 4; q++)
        *(float4*)&sm_r[w][q * 128 + lane * 4] = r4[q];
    __syncthreads();

    float M = fmaxf(fmaxf(sm_m[0], sm_m[1]), fmaxf(sm_m[2], sm_m[3]));
    float e0 = expf(sm_m[0] - M), e1 = expf(sm_m[1] - M);
    float e2 = expf(sm_m[2] - M), e3 = expf(sm_m[3] - M);
    float D = sm_d[0] * e0 + sm_d[1] * e1 + sm_d[2] * e2 + sm_d[3] * e3;
    float inv = D > 0.f ? 1.f / D : 0.f;

    float4 a0 = *(float4*)&sm_r[0][t * 4];
    float4 a1 = *(float4*)&sm_r[1][t * 4];
    float4 a2 = *(float4*)&sm_r[2][t * 4];
    float4 a3 = *(float4*)&sm_r[3][t * 4];
    float v0 = (a0.x * e0 + a1.x * e1 + a2.x * e2 + a3.x * e3) * inv;
    float v1 = (a0.y * e0 + a1.y * e1 + a2.y * e2 + a3.y * e3) * inv;
    float v2 = (a0.z * e0 + a1.z * e1 + a2.z * e2 + a3.z * e3) * inv;
    float v3 = (a0.w * e0 + a1.w * e1 + a2.w * e2 + a3.w * e3) * inv;

    if (mode == 2) {
        float4 r; r.x = v0; r.y = v1; r.z = v2; r.w = v3;
        *(float4*)(out + (size_t)b * 1024 + 512 + t * 4) = r;
    } else {
        float v[4] = {v0, v1, v2, v3};
        __nv_bfloat16 hi[4];
        #pragma unroll
        for (int k = 0; k < 4; k++) hi[k] = __float2bfloat16(v[k]);
        size_t base = (size_t)b * KG + 512 + t * 4;
        *(__nv_bfloat162*)(g_qhi + base)     = __halves2bfloat162(hi[0], hi[1]);
        *(__nv_bfloat162*)(g_qhi + base + 2) = __halves2bfloat162(hi[2], hi[3]);
        *(__nv_bfloat162*)(g_qlo + base) = __halves2bfloat162(
            __float2bfloat16(v[0] - __bfloat162float(hi[0])),
            __float2bfloat16(v[1] - __bfloat162float(hi[1])));
        *(__nv_bfloat162*)(g_qlo + base + 2) = __halves2bfloat162(
            __float2bfloat16(v[2] - __bfloat162float(hi[2])),
            __float2bfloat16(v[3] - __bfloat162float(hi[3])));
    }
}

// ---------------- GEMM: g_z[m][n] = q_star @ U  (mma.sync bf16 hi/lo 3-term, ldmatrix) ----------------
#define TILE_HB 10240                 // 128*80 bytes
#define BUF_HB  (4 * TILE_HB)         // 40960
#define SMEM_GEMM (2 * BUF_HB)        // 81920

__global__ __launch_bounds__(256, 2) void k_gemm() {
    extern __shared__ char dyn[];
    int t = threadIdx.x, lane = t & 31, w = t >> 5;
    int g = lane >> 2, tg = lane & 3;
    int quad = lane >> 3, rr = lane & 7;
    int m0 = blockIdx.x * 128, n0 = blockIdx.y * 128;
    int wm = (w & 1) * 64, wn = (w >> 1) * 32;
    uint32_t sbu = smem_u32(dyn);

    uint32_t a_off = (uint32_t)((rr + ((quad & 1) << 3)) * 80 + ((quad >> 1) << 4));
    uint32_t b_off = (uint32_t)((rr + ((quad >> 1) << 3)) * 80 + ((quad & 1) << 4));

    float acc[4][4][4];
    #pragma unroll
    for (int i = 0; i < 4; i++)
        #pragma unroll
        for (int j = 0; j < 4; j++)
            #pragma unroll
            for (int x = 0; x < 4; x++) acc[i][j][x] = 0.f;

    #define LOADCHUNK(tc, buf) do {                                             \
        _Pragma("unroll")                                                       \
        for (int it_ = 0; it_ < 8; it_++) {                                     \
            int idx_ = t + it_ * 256;                                           \
            int tile_ = idx_ >> 9;                                              \
            int r_ = (idx_ >> 2) & 127, c_ = idx_ & 3;                          \
            uint32_t dst_ = sbu + (buf) * BUF_HB + tile_ * TILE_HB              \
                          + (uint32_t)(r_ * 80 + c_ * 16);                      \
            size_t ka_ = (size_t)(tc) * 32 + c_ * 8;                            \
            const __nv_bfloat16* src_;                                          \
            if      (tile_ == 0) src_ = g_qhi + (size_t)(m0 + r_) * KG + ka_;   \
            else if (tile_ == 1) src_ = g_qlo + (size_t)(m0 + r_) * KG + ka_;   \
            else if (tile_ == 2) src_ = g_Bhi + (size_t)(n0 + r_) * KG + ka_;   \
            else                 src_ = g_Blo + (size_t)(n0 + r_) * KG + ka_;   \
            cp16(dst_, src_);                                                   \
        }                                                                       \
        cp_commit();                                                            \
    } while (0)

    LOADCHUNK(0, 0);
    for (int tc = 0; tc < 32; tc++) {
        if (tc + 1 < 32) {
            LOADCHUNK(tc + 1, (tc + 1) & 1);
            asm volatile("cp.async.wait_group 1;" ::: "memory");
        } else {
            asm volatile("cp.async.wait_group 0;" ::: "memory");
        }
        __syncthreads();
        uint32_t base = sbu + (tc & 1) * BUF_HB;
        #pragma unroll
        for (int ks = 0; ks < 2; ks++) {
            uint32_t ko = (uint32_t)(ks * 32);
            uint32_t ah[4][4], al[4][4], bq[2][4], bl[2][4];
            #pragma unroll
            for (int i = 0; i < 4; i++) {
                uint32_t ra = base + (uint32_t)((wm + i * 16) * 80) + a_off + ko;
                LDSM4(ah[i], ra);
                LDSM4(al[i], ra + TILE_HB);
            }
            #pragma unroll
            for (int jp = 0; jp < 2; jp++) {
                uint32_t rb = base + 2 * TILE_HB + (uint32_t)((wn + 16 * jp) * 80) + b_off + ko;
                LDSM4(bq[jp], rb);
                LDSM4(bl[jp], rb + TILE_HB);
            }
            #pragma unroll
            for (int i = 0; i < 4; i++)
                #pragma unroll
                for (int j = 0; j < 4; j++) {
                    const uint32_t* bh_ = &bq[j >> 1][(j & 1) * 2];
                    const uint32_t* bl_ = &bl[j >> 1][(j & 1) * 2];
                    MMA16816(acc[i][j], ah[i], bh_);
                    MMA16816(acc[i][j], ah[i], bl_);
                    MMA16816(acc[i][j], al[i], bh_);
                }
        }
        __syncthreads();
    }

    #pragma unroll
    for (int i = 0; i < 4; i++) {
        #pragma unroll
        for (int j = 0; j < 4; j++) {
            int row = m0 + wm + i * 16 + g;
            int col = n0 + wn + j * 8 + 2 * tg;
            float2 v01; v01.x = acc[i][j][0]; v01.y = acc[i][j][1];
            float2 v23; v23.x = acc[i][j][2]; v23.y = acc[i][j][3];
            *(float2*)(g_z + (size_t)row * NG + col)       = v01;
            *(float2*)(g_z + (size_t)(row + 8) * NG + col) = v23;
        }
    }
}

// ---------------- launch ----------------
extern "C" void kernel_launch(void* const* d_in, const int* in_sizes, int n_in,
                              void* d_out, int out_size) {
    const float* X     = (const float*)d_in[0];
    const int*   split = (const int*)d_in[1];   // int32 or int64; detected on device
    const float* U     = (const float*)d_in[2];
    const float* bias  = (const float*)d_in[3];
    float*       out   = (float*)d_out;
    (void)in_sizes; (void)n_in; (void)out_size;

    cudaFuncSetAttribute(k_gemm, cudaFuncAttributeMaxDynamicSharedMemorySize, SMEM_GEMM);

    k_init<<<512, 256>>>();
    k_off<<<(BATCH + 1 + 127) / 128, 128>>>(split);
    k_prep<<<dim3(KG / 32, NG / 32), 256>>>(U);
    for (int it = 0; it < 6; it++) {
        int mode = (it == 0) ? 0 : (it == 5 ? 2 : 1);
        k_attn<<<BATCH, 128>>>(X, bias, out, mode);
        if (it < 5) k_gemm<<<dim3(32, 16), 256, SMEM_GEMM>>>();
    }
}

// round 17
// speedup vs baseline: 1.0315x; 1.0315x over previous
#include <cuda_runtime.h>
#include <cuda_bf16.h>
#include <cstdint>

#define BATCH  4096
#define HID    512
#define NATOMS 262144
#define KG     1024
#define NG     2048

// ---------------- device scratch (no allocations allowed) ----------------
__device__ __align__(128) float g_c[BATCH * HID];     // c state [m][j]
__device__ __align__(128) float g_z[BATCH * NG];      // z = q@U scratch [m][4H] natural
__device__ __align__(128) __nv_bfloat16 g_qhi[BATCH * KG];  // q_star hi split [m][k]
__device__ __align__(128) __nv_bfloat16 g_qlo[BATCH * KG];  // q_star lo split
__device__ __align__(128) __nv_bfloat16 g_Bhi[NG * KG];     // U^T hi split [n][k] (natural n)
__device__ __align__(128) __nv_bfloat16 g_Blo[NG * KG];
__device__ int g_segoff[BATCH + 1];

// ---------------- helpers ----------------
__device__ __forceinline__ uint32_t smem_u32(const void* p) {
    uint32_t a;
    asm("{ .reg .u64 t; cvta.to.shared.u64 t, %1; cvt.u32.u64 %0, t; }" : "=r"(a) : "l"(p));
    return a;
}
__device__ __forceinline__ void cp16(uint32_t dst, const void* src) {
    asm volatile("cp.async.cg.shared.global [%0], [%1], 16;" :: "r"(dst), "l"(src));
}
__device__ __forceinline__ void cp_commit() {
    asm volatile("cp.async.commit_group;" ::: "memory");
}
#define MMA16816(d, a, b) \
    asm volatile("mma.sync.aligned.m16n8k16.row.col.f32.bf16.bf16.f32 " \
        "{%0,%1,%2,%3}, {%4,%5,%6,%7}, {%8,%9}, {%0,%1,%2,%3};" \
        : "+f"((d)[0]), "+f"((d)[1]), "+f"((d)[2]), "+f"((d)[3]) \
        : "r"((a)[0]), "r"((a)[1]), "r"((a)[2]), "r"((a)[3]), \
          "r"((b)[0]), "r"((b)[1]))
#define LDSM4(r, a) \
    asm volatile("ldmatrix.sync.aligned.m8n8.x4.shared.b16 {%0,%1,%2,%3}, [%4];" \
        : "=r"((r)[0]), "=r"((r)[1]), "=r"((r)[2]), "=r"((r)[3]) : "r"(a))

// ---------------- init / offsets / prep ----------------
__global__ void k_init() {
    int i = blockIdx.x * blockDim.x + threadIdx.x;
    int n = blockDim.x * gridDim.x;
    __nv_bfloat16 z = __float2bfloat16(0.f);
    for (int t = i; t < BATCH * HID; t += n) {
        g_c[t] = 0.f;
        int m = t >> 9, j = t & 511;
        g_qhi[(size_t)m * KG + j] = z;   // h part; r part written by attention
        g_qlo[(size_t)m * KG + j] = z;
    }
}

// dtype-agnostic segment offsets (atom_split may be int32 or int64)
__global__ void k_off(const int* __restrict__ s32) {
    __shared__ int is64;
    if (threadIdx.x == 0)
        is64 = (s32[2 * (NATOMS / 4) + 1] == 0) ? 1 : 0;
    __syncthreads();
    int b = blockIdx.x * blockDim.x + threadIdx.x;
    if (b > BATCH) return;
    int lo = 0, hi = NATOMS;
    while (lo < hi) {
        int mid = (lo + hi) >> 1;
        int v = is64 ? s32[2 * mid] : s32[mid];
        if (v < b) lo = mid + 1; else hi = mid;
    }
    g_segoff[b] = lo;
}

// B prep: tiled transpose + split; coalesced reads AND writes
__global__ __launch_bounds__(256) void k_prep(const float* __restrict__ U) {
    __shared__ float tile[32][33];
    int k0 = blockIdx.x * 32, n0 = blockIdx.y * 32;
    int tx = threadIdx.x & 31, ty = threadIdx.x >> 5;   // ty 0..7
    #pragma unroll
    for (int dy = 0; dy < 32; dy += 8)
        tile[ty + dy][tx] = U[(size_t)(k0 + ty + dy) * NG + n0 + tx];
    __syncthreads();
    #pragma unroll
    for (int dy = 0; dy < 32; dy += 8) {
        int n = n0 + ty + dy, k = k0 + tx;
        float v = tile[tx][ty + dy];
        __nv_bfloat16 hi = __float2bfloat16(v);
        g_Bhi[(size_t)n * KG + k] = hi;
        g_Blo[(size_t)n * KG + k] = __float2bfloat16(v - __bfloat162float(hi));
    }
}

// spacer: shifts launch index so ncu (-s 5 -c 1) captures the first k_gemm
__global__ void k_nop() {}

// ---------------- fused attention (+LSTM prologue) ----------------
// mode: 0 = first iter (h = 0), 1 = mid (LSTM prologue, write q splits),
//       2 = final (LSTM prologue, write h half of out; r half from attention)
__global__ __launch_bounds__(128, 8) void k_attn(const float* __restrict__ X,
                                                 const float* __restrict__ bias,
                                                 float* __restrict__ out, int mode) {
    int b = blockIdx.x, t = threadIdx.x;
    int lane = t & 31, w = t >> 5;
    __shared__ float sm_h[512];

    // ---- LSTM prologue (math verbatim; CTA owns row b) ----
    if (mode != 0) {
        const float* zr = g_z + (size_t)b * NG;
        float* cr = g_c + (size_t)b * HID;
        #pragma unroll
        for (int u = 0; u < 4; u++) {
            int j = t + u * 128;
            float zi = zr[j]        + bias[j];
            float zf = zr[512 + j]  + bias[512 + j];
            float zo = zr[1024 + j] + bias[1024 + j];
            float zg = zr[1536 + j] + bias[1536 + j];
            float gi = 1.f / (1.f + expf(-zi));
            float gf = 1.f / (1.f + expf(-zf));
            float go = 1.f / (1.f + expf(-zo));
            float c  = gf * cr[j] + gi * tanhf(zg);
            cr[j] = c;
            float h = go * tanhf(c);
            sm_h[j] = h;
            if (mode == 2) {
                out[(size_t)b * 1024 + j] = h;
            } else {
                __nv_bfloat16 hi = __float2bfloat16(h);
                g_qhi[(size_t)b * KG + j] = hi;
                g_qlo[(size_t)b * KG + j] = __float2bfloat16(h - __bfloat162float(hi));
            }
        }
    } else {
        #pragma unroll
        for (int u = 0; u < 4; u++) sm_h[t + u * 128] = 0.f;
    }
    __syncthreads();

    int s = g_segoff[b], e = g_segoff[b + 1];
    float4 h4[4];
    #pragma unroll
    for (int q = 0; q < 4; q++)
        h4[q] = *(const float4*)&sm_h[q * 128 + lane * 4];

    float mval = -1e30f, den = 0.f;
    float4 r4[4];
    #pragma unroll
    for (int q = 0; q < 4; q++) { r4[q].x = 0.f; r4[q].y = 0.f; r4[q].z = 0.f; r4[q].w = 0.f; }

    for (int a = s + w; a < e; a += 4) {
        const float4* xr = (const float4*)(X + (size_t)a * HID);
        float4 x4[4];
        #pragma unroll
        for (int q = 0; q < 4; q++)
            x4[q] = __ldcs(xr + q * 32 + lane);     // evict-first: X is streamed
        float p = 0.f;
        #pragma unroll
        for (int q = 0; q < 4; q++)
            p += x4[q].x * h4[q].x + x4[q].y * h4[q].y + x4[q].z * h4[q].z + x4[q].w * h4[q].w;
        #pragma unroll
        for (int o = 16; o; o >>= 1) p += __shfl_xor_sync(0xffffffffu, p, o);
        float mn = fmaxf(mval, p);
        float sc = expf(mval - mn);
        float pw = expf(p - mn);
        den = den * sc + pw;
        #pragma unroll
        for (int q = 0; q < 4; q++) {
            r4[q].x = r4[q].x * sc + pw * x4[q].x;
            r4[q].y = r4[q].y * sc + pw * x4[q].y;
            r4[q].z = r4[q].z * sc + pw * x4[q].z;
            r4[q].w = r4[q].w * sc + pw * x4[q].w;
        }
        mval = mn;
    }

    __shared__ float sm_m[4], sm_d[4];
    __shared__ float sm_r[4][512];
    if (lane == 0) { sm_m[w] = mval; sm_d[w] = den; }
    #pragma unroll
    for (int q = 0; q < 4; q++)
        *(float4*)&sm_r[w][q * 128 + lane * 4] = r4[q];
    __syncthreads();

    float M = fmaxf(fmaxf(sm_m[0], sm_m[1]), fmaxf(sm_m[2], sm_m[3]));
    float e0 = expf(sm_m[0] - M), e1 = expf(sm_m[1] - M);
    float e2 = expf(sm_m[2] - M), e3 = expf(sm_m[3] - M);
    float D = sm_d[0] * e0 + sm_d[1] * e1 + sm_d[2] * e2 + sm_d[3] * e3;
    float inv = D > 0.f ? 1.f / D : 0.f;

    float4 a0 = *(float4*)&sm_r[0][t * 4];
    float4 a1 = *(float4*)&sm_r[1][t * 4];
    float4 a2 = *(float4*)&sm_r[2][t * 4];
    float4 a3 = *(float4*)&sm_r[3][t * 4];
    float v0 = (a0.x * e0 + a1.x * e1 + a2.x * e2 + a3.x * e3) * inv;
    float v1 = (a0.y * e0 + a1.y * e1 + a2.y * e2 + a3.y * e3) * inv;
    float v2 = (a0.z * e0 + a1.z * e1 + a2.z * e2 + a3.z * e3) * inv;
    float v3 = (a0.w * e0 + a1.w * e1 + a2.w * e2 + a3.w * e3) * inv;

    if (mode == 2) {
        float4 r; r.x = v0; r.y = v1; r.z = v2; r.w = v3;
        *(float4*)(out + (size_t)b * 1024 + 512 + t * 4) = r;
    } else {
        float v[4] = {v0, v1, v2, v3};
        __nv_bfloat16 hi[4];
        #pragma unroll
        for (int k = 0; k < 4; k++) hi[k] = __float2bfloat16(v[k]);
        size_t base = (size_t)b * KG + 512 + t * 4;
        *(__nv_bfloat162*)(g_qhi + base)     = __halves2bfloat162(hi[0], hi[1]);
        *(__nv_bfloat162*)(g_qhi + base + 2) = __halves2bfloat162(hi[2], hi[3]);
        *(__nv_bfloat162*)(g_qlo + base) = __halves2bfloat162(
            __float2bfloat16(v[0] - __bfloat162float(hi[0])),
            __float2bfloat16(v[1] - __bfloat162float(hi[1])));
        *(__nv_bfloat162*)(g_qlo + base + 2) = __halves2bfloat162(
            __float2bfloat16(v[2] - __bfloat162float(hi[2])),
            __float2bfloat16(v[3] - __bfloat162float(hi[3])));
    }
}

// ---------------- GEMM: g_z[m][n] = q_star @ U  (mma.sync bf16 hi/lo 3-term, ldmatrix) ----------------
// Term-major MMA order: 16 independent MMAs between dependent same-acc pairs.
// Per-acc FP order (hh, hl, lh per k-step) unchanged -> bit-identical result.
#define TILE_HB 10240                 // 128*80 bytes
#define BUF_HB  (4 * TILE_HB)         // 40960
#define SMEM_GEMM (2 * BUF_HB)        // 81920

__global__ __launch_bounds__(256, 2) void k_gemm() {
    extern __shared__ char dyn[];
    int t = threadIdx.x, lane = t & 31, w = t >> 5;
    int g = lane >> 2, tg = lane & 3;
    int quad = lane >> 3, rr = lane & 7;
    int m0 = blockIdx.x * 128, n0 = blockIdx.y * 128;
    int wm = (w & 1) * 64, wn = (w >> 1) * 32;
    uint32_t sbu = smem_u32(dyn);

    uint32_t a_off = (uint32_t)((rr + ((quad & 1) << 3)) * 80 + ((quad >> 1) << 4));
    uint32_t b_off = (uint32_t)((rr + ((quad >> 1) << 3)) * 80 + ((quad & 1) << 4));

    float acc[4][4][4];
    #pragma unroll
    for (int i = 0; i < 4; i++)
        #pragma unroll
        for (int j = 0; j < 4; j++)
            #pragma unroll
            for (int x = 0; x < 4; x++) acc[i][j][x] = 0.f;

    #define LOADCHUNK(tc, buf) do {                                             \
        _Pragma("unroll")                                                       \
        for (int it_ = 0; it_ < 8; it_++) {                                     \
            int idx_ = t + it_ * 256;                                           \
            int tile_ = idx_ >> 9;                                              \
            int r_ = (idx_ >> 2) & 127, c_ = idx_ & 3;                          \
            uint32_t dst_ = sbu + (buf) * BUF_HB + tile_ * TILE_HB              \
                          + (uint32_t)(r_ * 80 + c_ * 16);                      \
            size_t ka_ = (size_t)(tc) * 32 + c_ * 8;                            \
            const __nv_bfloat16* src_;                                          \
            if      (tile_ == 0) src_ = g_qhi + (size_t)(m0 + r_) * KG + ka_;   \
            else if (tile_ == 1) src_ = g_qlo + (size_t)(m0 + r_) * KG + ka_;   \
            else if (tile_ == 2) src_ = g_Bhi + (size_t)(n0 + r_) * KG + ka_;   \
            else                 src_ = g_Blo + (size_t)(n0 + r_) * KG + ka_;   \
            cp16(dst_, src_);                                                   \
        }                                                                       \
        cp_commit();                                                            \
    } while (0)

    LOADCHUNK(0, 0);
    for (int tc = 0; tc < 32; tc++) {
        if (tc + 1 < 32) {
            LOADCHUNK(tc + 1, (tc + 1) & 1);
            asm volatile("cp.async.wait_group 1;" ::: "memory");
        } else {
            asm volatile("cp.async.wait_group 0;" ::: "memory");
        }
        __syncthreads();
        uint32_t base = sbu + (tc & 1) * BUF_HB;
        #pragma unroll
        for (int ks = 0; ks < 2; ks++) {
            uint32_t ko = (uint32_t)(ks * 32);
            uint32_t ah[4][4], al[4][4], bq[2][4], bl[2][4];
            #pragma unroll
            for (int i = 0; i < 4; i++) {
                uint32_t ra = base + (uint32_t)((wm + i * 16) * 80) + a_off + ko;
                LDSM4(ah[i], ra);
                LDSM4(al[i], ra + TILE_HB);
            }
            #pragma unroll
            for (int jp = 0; jp < 2; jp++) {
                uint32_t rb = base + 2 * TILE_HB + (uint32_t)((wn + 16 * jp) * 80) + b_off + ko;
                LDSM4(bq[jp], rb);
                LDSM4(bl[jp], rb + TILE_HB);
            }
            // term-major: 16 independent MMAs per term
            #pragma unroll
            for (int i = 0; i < 4; i++)
                #pragma unroll
                for (int j = 0; j < 4; j++)
                    MMA16816(acc[i][j], ah[i], &bq[j >> 1][(j & 1) * 2]);
            #pragma unroll
            for (int i = 0; i < 4; i++)
                #pragma unroll
                for (int j = 0; j < 4; j++)
                    MMA16816(acc[i][j], ah[i], &bl[j >> 1][(j & 1) * 2]);
            #pragma unroll
            for (int i = 0; i < 4; i++)
                #pragma unroll
                for (int j = 0; j < 4; j++)
                    MMA16816(acc[i][j], al[i], &bq[j >> 1][(j & 1) * 2]);
        }
        __syncthreads();
    }

    #pragma unroll
    for (int i = 0; i < 4; i++) {
        #pragma unroll
        for (int j = 0; j < 4; j++) {
            int row = m0 + wm + i * 16 + g;
            int col = n0 + wn + j * 8 + 2 * tg;
            float2 v01; v01.x = acc[i][j][0]; v01.y = acc[i][j][1];
            float2 v23; v23.x = acc[i][j][2]; v23.y = acc[i][j][3];
            *(float2*)(g_z + (size_t)row * NG + col)       = v01;
            *(float2*)(g_z + (size_t)(row + 8) * NG + col) = v23;
        }
    }
}

// ---------------- launch ----------------
extern "C" void kernel_launch(void* const* d_in, const int* in_sizes, int n_in,
                              void* d_out, int out_size) {
    const float* X     = (const float*)d_in[0];
    const int*   split = (const int*)d_in[1];   // int32 or int64; detected on device
    const float* U     = (const float*)d_in[2];
    const float* bias  = (const float*)d_in[3];
    float*       out   = (float*)d_out;
    (void)in_sizes; (void)n_in; (void)out_size;

    cudaFuncSetAttribute(k_gemm, cudaFuncAttributeMaxDynamicSharedMemorySize, SMEM_GEMM);

    k_init<<<512, 256>>>();
    k_off<<<(BATCH + 1 + 127) / 128, 128>>>(split);
    k_prep<<<dim3(KG / 32, NG / 32), 256>>>(U);
    k_nop<<<1, 32>>>();   // spacer: ncu -s 5 -c 1 now lands on the first k_gemm
    for (int it = 0; it < 6; it++) {
        int mode = (it == 0) ? 0 : (it == 5 ? 2 : 1);
        k_attn<<<BATCH, 128>>>(X, bias, out, mode);
        if (it < 5) k_gemm<<<dim3(32, 16), 256, SMEM_GEMM>>>();
    }
}